// round 17
// baseline (speedup 1.0000x reference)
#include <cuda_runtime.h>
#include <cstddef>

// Hin2vec layer: B=262144, N=1e6, R=64, H=128.
// R17: single-kernel R6. Regularization s*(1-s) computed inline from Wr
// (L1-resident 32KB, compute hides under the random gathers — R1/R2 evidence),
// loss finalized by the last block via device-scratch ticket (no prep kernel,
// no separate zeroing launch). Saves the ~2.2us serial prep launch.

#define H_DIM 128
#define R_DIM 64
#define WPB   8      // warps per block
#define ELEMS 4      // elements per warp

__device__ float    g_partial = 0.0f;   // zero-init at module load; self-resetting
__device__ unsigned g_count   = 0u;

__device__ __forceinline__ float sigd(float e) {
    e = fminf(fmaxf(e, -6.0f), 6.0f);
    const float s = 1.0f / (1.0f + __expf(-e));
    return s * (1.0f - s);
}

__device__ __forceinline__ float dot_rw(float4 a, float4 b, float4 w) {
    float acc = a.x * b.x * sigd(w.x);
    acc = fmaf(a.y * b.y, sigd(w.y), acc);
    acc = fmaf(a.z * b.z, sigd(w.z), acc);
    acc = fmaf(a.w * b.w, sigd(w.w), acc);
    return acc;
}

__global__ void __launch_bounds__(WPB * 32)
hin_main(const int* __restrict__ x,
         const int* __restrict__ y,
         const int* __restrict__ r,
         const int* __restrict__ l,
         const float4* __restrict__ Wx,   // [N, H/4]
         const float4* __restrict__ Wr,   // [R, H/4] (32KB, L1-resident)
         float* __restrict__ out,         // [B, 2] logits
         float* __restrict__ loss_out,    // scalar (may be null)
         int B, float invB)
{
    const int wid  = threadIdx.x >> 5;
    const int lane = threadIdx.x & 31;
    const int base = (blockIdx.x * WPB + wid) * ELEMS;

    __shared__ float sloss[WPB];
    float my_loss = 0.0f;

    if (base < B) {
        // Broadcast index loads (all lanes same address -> 1 sector each).
        const int4 xv = *(const int4*)(x + base);
        const int4 yv = *(const int4*)(y + base);

        // Issue all 8 random 512B gathers before any dependent work (MLP=8).
        const float4 ax0 = __ldcg(Wx + (unsigned)xv.x * (H_DIM / 4) + lane);
        const float4 ay0 = __ldcg(Wx + (unsigned)yv.x * (H_DIM / 4) + lane);
        const float4 ax1 = __ldcg(Wx + (unsigned)xv.y * (H_DIM / 4) + lane);
        const float4 ay1 = __ldcg(Wx + (unsigned)yv.y * (H_DIM / 4) + lane);
        const float4 ax2 = __ldcg(Wx + (unsigned)xv.z * (H_DIM / 4) + lane);
        const float4 ay2 = __ldcg(Wx + (unsigned)yv.z * (H_DIM / 4) + lane);
        const float4 ax3 = __ldcg(Wx + (unsigned)xv.w * (H_DIM / 4) + lane);
        const float4 ay3 = __ldcg(Wx + (unsigned)yv.w * (H_DIM / 4) + lane);

        // Wr rows (hot 32KB, L1-resident); sigd computed inline — the
        // MUFU/FMA work hides under the outstanding gathers.
        const int4 rv = *(const int4*)(r + base);
        const float4 wr0 = __ldg(Wr + (unsigned)rv.x * (H_DIM / 4) + lane);
        const float4 wr1 = __ldg(Wr + (unsigned)rv.y * (H_DIM / 4) + lane);
        const float4 wr2 = __ldg(Wr + (unsigned)rv.z * (H_DIM / 4) + lane);
        const float4 wr3 = __ldg(Wr + (unsigned)rv.w * (H_DIM / 4) + lane);

        float a0 = dot_rw(ax0, ay0, wr0);
        float a1 = dot_rw(ax1, ay1, wr1);
        float a2 = dot_rw(ax2, ay2, wr2);
        float a3 = dot_rw(ax3, ay3, wr3);

        // Four interleaved butterfly reductions (latencies overlap).
        #pragma unroll
        for (int o = 16; o > 0; o >>= 1) {
            a0 += __shfl_xor_sync(0xFFFFFFFFu, a0, o);
            a1 += __shfl_xor_sync(0xFFFFFFFFu, a1, o);
            a2 += __shfl_xor_sync(0xFFFFFFFFu, a2, o);
            a3 += __shfl_xor_sync(0xFFFFFFFFu, a3, o);
        }

        // Lanes 0..3 each finish one element in parallel.
        if (lane < ELEMS) {
            const float acc = (lane == 0) ? a0 : (lane == 1) ? a1 : (lane == 2) ? a2 : a3;
            const float p = 1.0f / (1.0f + __expf(-acc));

            float2 lg;                     // coalesced 4x float2 -> one 32B sector
            lg.x = p;
            lg.y = 1.0f - p;
            reinterpret_cast<float2*>(out)[base + lane] = lg;

            if (loss_out) {
                const float ea  = __expf(p);
                const float eb  = __expf(1.0f - p);
                const float lse = __logf(ea + eb);
                const int   li  = __ldg(l + base + lane);
                const float chosen = (li == 0) ? p : (1.0f - p);
                my_loss = (lse - chosen) * invB;
            }
        }
    }

    if (loss_out) {
        // Fold lanes 0..3 partials into lane 0 (others carry 0).
        my_loss += __shfl_xor_sync(0xFFFFFFFFu, my_loss, 1);
        my_loss += __shfl_xor_sync(0xFFFFFFFFu, my_loss, 2);
        if (lane == 0) sloss[wid] = my_loss;
        __syncthreads();
        if (threadIdx.x == 0) {
            float s = 0.0f;
            #pragma unroll
            for (int w = 0; w < WPB; w++) s += sloss[w];
            atomicAdd(&g_partial, s);
            __threadfence();
            const unsigned ticket = atomicAdd(&g_count, 1u);
            if (ticket == gridDim.x - 1) {
                // Last block: publish and reset for the next graph replay.
                const float total = atomicExch(&g_partial, 0.0f);
                *loss_out = total;
                g_count = 0u;
                __threadfence();
            }
        }
    }
}

extern "C" void kernel_launch(void* const* d_in, const int* in_sizes, int n_in,
                              void* d_out, int out_size)
{
    const int*    x  = (const int*)d_in[0];
    const int*    y  = (const int*)d_in[1];
    const int*    r  = (const int*)d_in[2];
    const int*    l  = (const int*)d_in[3];
    const float4* Wx = (const float4*)d_in[4];
    const float4* Wr = (const float4*)d_in[5];

    const int B = in_sizes[0];
    float* out = (float*)d_out;
    float* loss_ptr = (out_size > 2 * B) ? (out + 2 * B) : nullptr;

    const int elems_per_block = WPB * ELEMS;
    const int blocks = (B + elems_per_block - 1) / elems_per_block;
    hin_main<<<blocks, WPB * 32>>>(
        x, y, r, l, Wx, Wr, out, loss_ptr, B, 1.0f / (float)B);
}